// round 2
// baseline (speedup 1.0000x reference)
#include <cuda_runtime.h>
#include <cuda_bf16.h>
#include <cstdint>

// ===================== Problem constants =====================

#define BATCH 4096
#define NTOT  8192
#define DIM   128
#define BM    128
#define BN    128
#define SPLITS 2
#define TILES_PER_CTA (NTOT / SPLITS / BN)   // 32

#define ROW_BYTES 272                        // 128 bf16 = 256B, +16B pad (conflict-free ldmatrix)
#define SM_A_OFF   0
#define SM_B0_OFF  (128 * ROW_BYTES)         // 34816
#define SM_B1_OFF  (2 * 128 * ROW_BYTES)     // 69632
#define SM_RSUM_OFF (3 * 128 * ROW_BYTES)    // 104448
#define SMEM_BYTES (SM_RSUM_OFF + 128 * 4)   // 104960

// e^2 (exact self-similarity exp to subtract)
#define EXP_DIAG 7.3890560989306495f

// ===================== small asm helpers (sm_100-safe, no 'a' features) =====================

__device__ __forceinline__ uint32_t smem_u32(const void* smem_ptr) {
    uint32_t addr;
    asm("{ .reg .u64 tmp; cvta.to.shared.u64 tmp, %1; cvt.u32.u64 %0, tmp; }"
        : "=r"(addr) : "l"(smem_ptr));
    return addr;
}

#define LDSM_X4(r, addr) \
    asm volatile("ldmatrix.sync.aligned.m8n8.x4.shared.b16 {%0,%1,%2,%3}, [%4];" \
        : "=r"((r)[0]), "=r"((r)[1]), "=r"((r)[2]), "=r"((r)[3]) : "r"(addr))

#define MMA_BF16(d, a, b0, b1) \
    asm volatile("mma.sync.aligned.m16n8k16.row.col.f32.bf16.bf16.f32 " \
        "{%0,%1,%2,%3}, {%4,%5,%6,%7}, {%8,%9}, {%0,%1,%2,%3};" \
        : "+f"((d)[0]), "+f"((d)[1]), "+f"((d)[2]), "+f"((d)[3]) \
        : "r"((a)[0]), "r"((a)[1]), "r"((a)[2]), "r"((a)[3]), "r"(b0), "r"(b1))

#define CP_ASYNC_16(dst_smem, src_gmem) \
    asm volatile("cp.async.cg.shared.global [%0], [%1], 16;" \
        :: "r"(dst_smem), "l"(src_gmem) : "memory")

#define CP_ASYNC_COMMIT() asm volatile("cp.async.commit_group;" ::: "memory")
#define CP_ASYNC_WAIT_1() asm volatile("cp.async.wait_group 1;" ::: "memory")
#define CP_ASYNC_WAIT_0() asm volatile("cp.async.wait_group 0;" ::: "memory")

// ===================== Device scratch (no allocs allowed) =====================

__device__ __nv_bfloat16 g_zn[NTOT * DIM];   // normalized rows, bf16
__device__ float g_pos[BATCH];               // pos_r = sim(r, r+B) already /T, fp32 exact
__device__ float g_rowsum[SPLITS][NTOT];     // partial sum-of-exp per row

// ===================== K1: normalize + positives =====================

__global__ void __launch_bounds__(128) k1_normalize(const float* __restrict__ zi,
                                                    const float* __restrict__ zj) {
    const int r = blockIdx.x;
    const int t = threadIdx.x;
    float a = zi[r * DIM + t];
    float b = zj[r * DIM + t];
    float sa = a * a, sb = b * b, sab = a * b;
    #pragma unroll
    for (int o = 16; o; o >>= 1) {
        sa  += __shfl_xor_sync(0xffffffffu, sa,  o);
        sb  += __shfl_xor_sync(0xffffffffu, sb,  o);
        sab += __shfl_xor_sync(0xffffffffu, sab, o);
    }
    __shared__ float red[3][4];
    const int w = t >> 5, l = t & 31;
    if (l == 0) { red[0][w] = sa; red[1][w] = sb; red[2][w] = sab; }
    __syncthreads();
    sa  = red[0][0] + red[0][1] + red[0][2] + red[0][3];
    sb  = red[1][0] + red[1][1] + red[1][2] + red[1][3];
    sab = red[2][0] + red[2][1] + red[2][2] + red[2][3];
    const float ri = rsqrtf(fmaxf(sa, 1e-16f));
    const float rj = rsqrtf(fmaxf(sb, 1e-16f));
    g_zn[r * DIM + t]           = __float2bfloat16(a * ri);
    g_zn[(r + BATCH) * DIM + t] = __float2bfloat16(b * rj);
    if (t == 0) g_pos[r] = sab * ri * rj * 2.0f;   // /T = *2
}

// ===================== K2: fused bf16-MMA GEMM + exp + row-sum =====================
//
// grid: 128 CTAs = 64 row-stripes x 2 column splits. 256 threads = 8 warps.
// Warp grid 4x2 (M x N): warp (wm, wn) owns rows wm*32..+31, cols wn*64..+63
// of each 128x128 sim tile. Accumulators in registers (64 fp32/thread).
// Row-sum partials also live in registers across all 32 tiles.

__global__ void __launch_bounds__(256, 1) k2_simsum() {
    extern __shared__ __align__(16) char dynsm[];
    char* smA = dynsm + SM_A_OFF;
    float* rsum = reinterpret_cast<float*>(dynsm + SM_RSUM_OFF);

    const int tid = threadIdx.x;
    const int wid = tid >> 5;
    const int lane = tid & 31;
    const int wm = wid & 3;        // 4 row bands of 32
    const int wn = wid >> 2;       // 2 col halves of 64
    const int stripe = blockIdx.x >> 1;
    const int split  = blockIdx.x & 1;
    const int i0 = stripe * BM;

    if (tid < 128) rsum[tid] = 0.0f;

    // ---- issue cp.async for B tile t into buffer buf ----
    auto issueB = [&](int t, char* buf) {
        const int j0 = split * (NTOT / SPLITS) + t * BN;
        #pragma unroll
        for (int i = 0; i < 8; i++) {
            const int idx = tid + i * 256;           // 2048 16B chunks
            const int row = idx >> 4;
            const int c   = idx & 15;
            const uint32_t dst = smem_u32(buf + row * ROW_BYTES + c * 16);
            const uint4* src = reinterpret_cast<const uint4*>(g_zn + (j0 + row) * DIM) + c;
            CP_ASYNC_16(dst, src);
        }
        CP_ASYNC_COMMIT();
    };

    // prefetch B tile 0
    issueB(0, dynsm + SM_B0_OFF);

    // ---- load A stripe [128 x 128] bf16 into smem (plain stores) ----
    #pragma unroll
    for (int i = 0; i < 8; i++) {
        const int idx = tid + i * 256;
        const int row = idx >> 4;
        const int c   = idx & 15;
        *reinterpret_cast<uint4*>(smA + row * ROW_BYTES + c * 16) =
            reinterpret_cast<const uint4*>(g_zn + (i0 + row) * DIM)[c];
    }

    // ---- precompute per-lane ldmatrix base addresses ----
    // A x4 (m16k16): row = wm*32 + mb*16 + ((lane>>3)&1)*8 + (lane&7); kbyte = (lane>>4)*16
    const uint32_t aBase = smem_u32(smA)
        + (uint32_t)((wm * 32 + ((lane >> 3) & 1) * 8 + (lane & 7)) * ROW_BYTES)
        + (uint32_t)((lane >> 4) * 16);
    // B x4 (two n8k16 frags): n = wn*64 + nb*16 + (lane>>4)*8 + (lane&7); kbyte = ((lane>>3)&1)*16
    const uint32_t bLane =
        (uint32_t)(((wn * 64) + (lane >> 4) * 8 + (lane & 7)) * ROW_BYTES)
        + (uint32_t)(((lane >> 3) & 1) * 16);

    float prow[4] = {0.f, 0.f, 0.f, 0.f};   // running row partials (mb x {r0,r1})

    // exp(v) Taylor deg-7 on |v|<=~1, then exp(2v) = p*p (rel err ~5e-5)
    const float C7 = 1.0f / 5040.0f, C6 = 1.0f / 720.0f, C5 = 1.0f / 120.0f;
    const float C4 = 1.0f / 24.0f,   C3 = 1.0f / 6.0f,   C2 = 0.5f;

    for (int t = 0; t < TILES_PER_CTA; t++) {
        if (t + 1 < TILES_PER_CTA) {
            issueB(t + 1, dynsm + ((t + 1) & 1 ? SM_B1_OFF : SM_B0_OFF));
            CP_ASYNC_WAIT_1();          // tile t complete
        } else {
            CP_ASYNC_WAIT_0();
        }
        __syncthreads();                // B tile t (and A on t=0) visible to all

        float acc[2][8][4];
        #pragma unroll
        for (int mb = 0; mb < 2; mb++)
            #pragma unroll
            for (int j = 0; j < 8; j++)
                #pragma unroll
                for (int v = 0; v < 4; v++) acc[mb][j][v] = 0.0f;

        const uint32_t bBase = smem_u32(dynsm + ((t & 1) ? SM_B1_OFF : SM_B0_OFF)) + bLane;

        #pragma unroll
        for (int ks = 0; ks < 8; ks++) {
            uint32_t a0[4], a1[4];
            LDSM_X4(a0, aBase + ks * 32);
            LDSM_X4(a1, aBase + 16 * ROW_BYTES + ks * 32);
            #pragma unroll
            for (int nb = 0; nb < 4; nb++) {
                uint32_t b[4];
                LDSM_X4(b, bBase + nb * 16 * ROW_BYTES + ks * 32);
                MMA_BF16(acc[0][2 * nb],     a0, b[0], b[1]);
                MMA_BF16(acc[0][2 * nb + 1], a0, b[2], b[3]);
                MMA_BF16(acc[1][2 * nb],     a1, b[0], b[1]);
                MMA_BF16(acc[1][2 * nb + 1], a1, b[2], b[3]);
            }
        }

        // ---- epilogue: exp(2*dot) and fold into running row partials ----
        #pragma unroll
        for (int mb = 0; mb < 2; mb++)
            #pragma unroll
            for (int j = 0; j < 8; j++)
                #pragma unroll
                for (int v = 0; v < 4; v++) {
                    const float x = acc[mb][j][v];
                    float p = fmaf(C7, x, C6);
                    p = fmaf(p, x, C5);
                    p = fmaf(p, x, C4);
                    p = fmaf(p, x, C3);
                    p = fmaf(p, x, C2);
                    p = fmaf(p, x, 1.0f);
                    p = fmaf(p, x, 1.0f);            // p ~= exp(x)
                    prow[mb * 2 + (v >> 1)] = fmaf(p, p, prow[mb * 2 + (v >> 1)]);
                }

        __syncthreads();                // done reading buf (t&1) before t+2 overwrites it
    }

    // ---- combine lanes (same row spread across lane%4 quads) ----
    #pragma unroll
    for (int k = 0; k < 4; k++) {
        prow[k] += __shfl_xor_sync(0xffffffffu, prow[k], 1);
        prow[k] += __shfl_xor_sync(0xffffffffu, prow[k], 2);
    }
    if ((lane & 3) == 0) {
        const int g = lane >> 2;
        atomicAdd(&rsum[wm * 32 + g],          prow[0]);
        atomicAdd(&rsum[wm * 32 + g + 8],      prow[1]);
        atomicAdd(&rsum[wm * 32 + 16 + g],     prow[2]);
        atomicAdd(&rsum[wm * 32 + 16 + g + 8], prow[3]);
    }
    __syncthreads();
    if (tid < 128) g_rowsum[split][i0 + tid] = rsum[tid];
}

// ===================== K3: log + final reduction =====================

__global__ void __launch_bounds__(256) k3_reduce(float* __restrict__ out) {
    const int t = threadIdx.x;
    float s = 0.0f;
    for (int i = t; i < NTOT; i += 256) {
        const float rs = g_rowsum[0][i] + g_rowsum[1][i] - EXP_DIAG;
        s += logf(rs);
    }
    for (int r = t; r < BATCH; r += 256) s -= 2.0f * g_pos[r];
    #pragma unroll
    for (int o = 16; o; o >>= 1) s += __shfl_xor_sync(0xffffffffu, s, o);
    __shared__ float red[8];
    if ((t & 31) == 0) red[t >> 5] = s;
    __syncthreads();
    if (t == 0) {
        float tot = 0.0f;
        #pragma unroll
        for (int w = 0; w < 8; w++) tot += red[w];
        out[0] = tot / (float)NTOT;
    }
}

// ===================== launch =====================

extern "C" void kernel_launch(void* const* d_in, const int* in_sizes, int n_in,
                              void* d_out, int out_size) {
    const float* zi = (const float*)d_in[0];
    const float* zj = (const float*)d_in[1];
    float* out = (float*)d_out;

    // raise dynamic smem limit for K2 (attribute set, not an allocation)
    cudaFuncSetAttribute(k2_simsum, cudaFuncAttributeMaxDynamicSharedMemorySize, SMEM_BYTES);

    k1_normalize<<<BATCH, 128>>>(zi, zj);
    k2_simsum<<<SPLITS * (NTOT / BM), 256, SMEM_BYTES>>>();
    k3_reduce<<<1, 256>>>(out);
}

// round 3
// speedup vs baseline: 1.6671x; 1.6671x over previous
#include <cuda_runtime.h>
#include <cuda_bf16.h>
#include <cstdint>

// ===================== Problem constants =====================

#define BATCH 4096
#define NTOT  8192
#define DIM   128
#define NSTRIPES 64                       // 8192 / 128
#define NTILES 2080                       // 64*65/2, upper triangle incl diagonal
#define GRID_K2 148

#define ROW_BYTES 272                     // 256B row + 16B pad (conflict-free ldmatrix)
#define TILE_BYTES (128 * ROW_BYTES)      // 34816
#define SM_CSUM_OFF (4 * TILE_BYTES)      // [A0][B0][A1][B1][csum2[4][128]]
#define SMEM_BYTES (SM_CSUM_OFF + 4 * 128 * 4)

#define EXP_DIAG 7.3890560989306495f      // e^2, self-similarity exp

// ===================== asm helpers (sm_100-safe, no 'a' features) =====================

__device__ __forceinline__ uint32_t smem_u32(const void* smem_ptr) {
    uint32_t addr;
    asm("{ .reg .u64 tmp; cvta.to.shared.u64 tmp, %1; cvt.u32.u64 %0, tmp; }"
        : "=r"(addr) : "l"(smem_ptr));
    return addr;
}

#define LDSM_X4(r, addr) \
    asm volatile("ldmatrix.sync.aligned.m8n8.x4.shared.b16 {%0,%1,%2,%3}, [%4];" \
        : "=r"((r)[0]), "=r"((r)[1]), "=r"((r)[2]), "=r"((r)[3]) : "r"(addr))

#define MMA_BF16(d, a, b0, b1) \
    asm volatile("mma.sync.aligned.m16n8k16.row.col.f32.bf16.bf16.f32 " \
        "{%0,%1,%2,%3}, {%4,%5,%6,%7}, {%8,%9}, {%0,%1,%2,%3};" \
        : "+f"((d)[0]), "+f"((d)[1]), "+f"((d)[2]), "+f"((d)[3]) \
        : "r"((a)[0]), "r"((a)[1]), "r"((a)[2]), "r"((a)[3]), "r"(b0), "r"(b1))

#define CP_ASYNC_16(dst_smem, src_gmem) \
    asm volatile("cp.async.cg.shared.global [%0], [%1], 16;" \
        :: "r"(dst_smem), "l"(src_gmem) : "memory")

#define CP_ASYNC_COMMIT() asm volatile("cp.async.commit_group;" ::: "memory")
#define CP_ASYNC_WAIT_1() asm volatile("cp.async.wait_group 1;" ::: "memory")
#define CP_ASYNC_WAIT_0() asm volatile("cp.async.wait_group 0;" ::: "memory")

// ---- packed f32x2 (PTX ISA: sm_100+, not 'a'-gated; ptxas never auto-emits) ----

typedef unsigned long long u64;

__device__ __forceinline__ u64 pk2(float lo, float hi) {
    u64 r;
    asm("mov.b64 %0, {%1, %2};" : "=l"(r) : "f"(lo), "f"(hi));
    return r;
}
__device__ __forceinline__ void upk2(float& lo, float& hi, u64 v) {
    asm("mov.b64 {%0, %1}, %2;" : "=f"(lo), "=f"(hi) : "l"(v));
}
__device__ __forceinline__ u64 fma2(u64 a, u64 b, u64 c) {
    u64 d;
    asm("fma.rn.f32x2 %0, %1, %2, %3;" : "=l"(d) : "l"(a), "l"(b), "l"(c));
    return d;
}
__device__ __forceinline__ constexpr u64 dup2c(float f) {
    // compile-time duplicate of a float constant into both lanes
    union { float f32; unsigned int u32; } u = { f };
    return ((u64)u.u32 << 32) | u.u32;
}

// ===================== Device scratch =====================

__device__ __nv_bfloat16 g_zn[NTOT * DIM];   // normalized rows, bf16
__device__ float g_pos[BATCH];               // pos_r = sim(r, r+B)/T, fp32 exact
__device__ float g_rowsum[NTOT];             // sum of exp per row (atomics)

// ===================== K1: normalize + positives (warp-per-row) =====================

__global__ void __launch_bounds__(256) k1_normalize(const float* __restrict__ zi,
                                                    const float* __restrict__ zj) {
    const int tid = threadIdx.x;
    const int lane = tid & 31;
    const int r = blockIdx.x * 8 + (tid >> 5);   // 512 blocks x 8 warps

    const float4 va = reinterpret_cast<const float4*>(zi + r * DIM)[lane];
    const float4 vb = reinterpret_cast<const float4*>(zj + r * DIM)[lane];
    float sa  = va.x*va.x + va.y*va.y + va.z*va.z + va.w*va.w;
    float sb  = vb.x*vb.x + vb.y*vb.y + vb.z*vb.z + vb.w*vb.w;
    float sab = va.x*vb.x + va.y*vb.y + va.z*vb.z + va.w*vb.w;
    #pragma unroll
    for (int o = 16; o; o >>= 1) {
        sa  += __shfl_xor_sync(0xffffffffu, sa,  o);
        sb  += __shfl_xor_sync(0xffffffffu, sb,  o);
        sab += __shfl_xor_sync(0xffffffffu, sab, o);
    }
    const float ri = rsqrtf(fmaxf(sa, 1e-16f));
    const float rj = rsqrtf(fmaxf(sb, 1e-16f));

    __nv_bfloat162 a01 = __floats2bfloat162_rn(va.x * ri, va.y * ri);
    __nv_bfloat162 a23 = __floats2bfloat162_rn(va.z * ri, va.w * ri);
    __nv_bfloat162 b01 = __floats2bfloat162_rn(vb.x * rj, vb.y * rj);
    __nv_bfloat162 b23 = __floats2bfloat162_rn(vb.z * rj, vb.w * rj);
    reinterpret_cast<uint2*>(g_zn + r * DIM)[lane] =
        make_uint2(*reinterpret_cast<uint32_t*>(&a01), *reinterpret_cast<uint32_t*>(&a23));
    reinterpret_cast<uint2*>(g_zn + (r + BATCH) * DIM)[lane] =
        make_uint2(*reinterpret_cast<uint32_t*>(&b01), *reinterpret_cast<uint32_t*>(&b23));

    if (lane == 0) g_pos[r] = sab * ri * rj * 2.0f;   // /T = *2
    if (blockIdx.x < 32) g_rowsum[blockIdx.x * 256 + tid] = 0.0f;   // zero for K2 atomics
}

// ===================== K2: symmetric fused GEMM + exp + row/col sums =====================
//
// Persistent 148 CTAs, strided over 2080 upper-triangle 128x128 tiles (J >= I).
// Off-diagonal tile: row sums -> rows of stripe I, col sums -> rows of stripe J.
// 8 warps as 4x2 (M x N); accumulators + packed f32x2 exp epilogue in registers.

__device__ __forceinline__ void decode_tile(int t, int& I, int& J) {
    int i = (int)(64.5f - sqrtf(64.5f * 64.5f - 2.0f * (float)t));
    while (i * (129 - i) / 2 > t) i--;
    while ((i + 1) * (128 - i) / 2 <= t) i++;   // C(i+1) = (i+1)(129-(i+1))/2
    I = i;
    J = i + (t - i * (129 - i) / 2);
}

__global__ void __launch_bounds__(256, 1) k2_simsum() {
    extern __shared__ __align__(16) char dynsm[];
    float (*csum2)[128] = reinterpret_cast<float(*)[128]>(dynsm + SM_CSUM_OFF);

    const int tid = threadIdx.x;
    const int wid = tid >> 5;
    const int lane = tid & 31;
    const int wm = wid & 3;        // 4 row bands of 32
    const int wn = wid >> 2;       // 2 col halves of 64

    // cp.async one tile's A (stripe I) and, if J!=I, B (stripe J); one commit group.
    auto issue = [&](int slot, int I, int J) {
        char* bufA = dynsm + slot * (2 * TILE_BYTES);
        #pragma unroll
        for (int i = 0; i < 8; i++) {
            const int idx = tid + i * 256, row = idx >> 4, c = idx & 15;
            CP_ASYNC_16(smem_u32(bufA + row * ROW_BYTES + c * 16),
                        reinterpret_cast<const uint4*>(g_zn + (I * 128 + row) * DIM) + c);
        }
        if (J != I) {
            char* bufB = bufA + TILE_BYTES;
            #pragma unroll
            for (int i = 0; i < 8; i++) {
                const int idx = tid + i * 256, row = idx >> 4, c = idx & 15;
                CP_ASYNC_16(smem_u32(bufB + row * ROW_BYTES + c * 16),
                            reinterpret_cast<const uint4*>(g_zn + (J * 128 + row) * DIM) + c);
            }
        }
        CP_ASYNC_COMMIT();
    };

    // per-lane ldmatrix offsets within a stripe buffer
    const uint32_t aLane =
        (uint32_t)((wm * 32 + ((lane >> 3) & 1) * 8 + (lane & 7)) * ROW_BYTES)
        + (uint32_t)((lane >> 4) * 16);
    const uint32_t bLane =
        (uint32_t)(((wn * 64) + (lane >> 4) * 8 + (lane & 7)) * ROW_BYTES)
        + (uint32_t)(((lane >> 3) & 1) * 16);

    // packed exp(x) Taylor deg-7 on |x|<=1; exp(2x) = p*p folded into accumulators
    const u64 C7 = dup2c(1.0f / 5040.0f), C6 = dup2c(1.0f / 720.0f),
              C5 = dup2c(1.0f / 120.0f),  C4 = dup2c(1.0f / 24.0f),
              C3 = dup2c(1.0f / 6.0f),    C2 = dup2c(0.5f), C1 = dup2c(1.0f);

    int t = blockIdx.x;
    int I, J, In, Jn;
    decode_tile(t, I, J);
    issue(0, I, J);
    int slot = 0;

    for (; t < NTILES; t += GRID_K2) {
        const int tn = t + GRID_K2;
        if (tn < NTILES) {
            decode_tile(tn, In, Jn);
            issue(slot ^ 1, In, Jn);
            CP_ASYNC_WAIT_1();
        } else {
            CP_ASYNC_WAIT_0();
        }
        __syncthreads();

        const char* base = dynsm + slot * (2 * TILE_BYTES);
        const uint32_t aBase = smem_u32(base) + aLane;
        const uint32_t bBase = smem_u32(base + (J != I ? TILE_BYTES : 0)) + bLane;

        float acc[2][8][4];
        #pragma unroll
        for (int mb = 0; mb < 2; mb++)
            #pragma unroll
            for (int j = 0; j < 8; j++)
                #pragma unroll
                for (int v = 0; v < 4; v++) acc[mb][j][v] = 0.0f;

        #pragma unroll
        for (int ks = 0; ks < 8; ks++) {
            uint32_t a0[4], a1[4];
            LDSM_X4(a0, aBase + ks * 32);
            LDSM_X4(a1, aBase + 16 * ROW_BYTES + ks * 32);
            #pragma unroll
            for (int nb = 0; nb < 4; nb++) {
                uint32_t b[4];
                LDSM_X4(b, bBase + nb * 16 * ROW_BYTES + ks * 32);
                MMA_BF16(acc[0][2 * nb],     a0, b[0], b[1]);
                MMA_BF16(acc[0][2 * nb + 1], a0, b[2], b[3]);
                MMA_BF16(acc[1][2 * nb],     a1, b[0], b[1]);
                MMA_BF16(acc[1][2 * nb + 1], a1, b[2], b[3]);
            }
        }

        // ---- packed epilogue: exp(2x), fold into row/col partials ----
        u64 prow[4] = {0ull, 0ull, 0ull, 0ull};   // [mb*2 + rowhalf]
        u64 pcol[8];                              // per jj (2 cols/thread), both rows folded
        #pragma unroll
        for (int j = 0; j < 8; j++) pcol[j] = 0ull;

        #pragma unroll
        for (int mb = 0; mb < 2; mb++)
            #pragma unroll
            for (int jj = 0; jj < 8; jj++)
                #pragma unroll
                for (int vp = 0; vp < 2; vp++) {
                    u64 x = pk2(acc[mb][jj][2 * vp], acc[mb][jj][2 * vp + 1]);
                    u64 p = fma2(C7, x, C6);
                    p = fma2(p, x, C5);
                    p = fma2(p, x, C4);
                    p = fma2(p, x, C3);
                    p = fma2(p, x, C2);
                    p = fma2(p, x, C1);
                    p = fma2(p, x, C1);                 // p ~= exp(x)
                    prow[mb * 2 + vp] = fma2(p, p, prow[mb * 2 + vp]);  // += exp(2x)
                    pcol[jj]          = fma2(p, p, pcol[jj]);
                }

        // ---- row sums: reduce over quad (lane&3), atomicAdd to stripe I rows ----
        #pragma unroll
        for (int k = 0; k < 4; k++) {
            prow[k] = fma2(dup2c(1.0f), __shfl_xor_sync(0xffffffffu, prow[k], 1), prow[k]);
            prow[k] = fma2(dup2c(1.0f), __shfl_xor_sync(0xffffffffu, prow[k], 2), prow[k]);
        }
        if ((lane & 3) == 0) {
            const int g = lane >> 2;
            const int rbase = I * 128 + wm * 32;
            float lo, hi;
            upk2(lo, hi, prow[0]); atomicAdd(&g_rowsum[rbase + g],      lo + hi);
            upk2(lo, hi, prow[1]); atomicAdd(&g_rowsum[rbase + g + 8],  lo + hi);
            upk2(lo, hi, prow[2]); atomicAdd(&g_rowsum[rbase + 16 + g], lo + hi);
            upk2(lo, hi, prow[3]); atomicAdd(&g_rowsum[rbase + 24 + g], lo + hi);
        }

        // ---- col sums (off-diagonal only): reduce over lane>>2, flush to stripe J ----
        if (J != I) {
            #pragma unroll
            for (int j = 0; j < 8; j++) {
                pcol[j] = fma2(dup2c(1.0f), __shfl_xor_sync(0xffffffffu, pcol[j], 4),  pcol[j]);
                pcol[j] = fma2(dup2c(1.0f), __shfl_xor_sync(0xffffffffu, pcol[j], 8),  pcol[j]);
                pcol[j] = fma2(dup2c(1.0f), __shfl_xor_sync(0xffffffffu, pcol[j], 16), pcol[j]);
            }
            if (lane < 4) {
                #pragma unroll
                for (int j = 0; j < 8; j++) {
                    float lo, hi;
                    upk2(lo, hi, pcol[j]);
                    const int c = wn * 64 + (j >> 1) * 16 + (j & 1) * 8 + lane * 2;
                    csum2[wm][c]     = lo;
                    csum2[wm][c + 1] = hi;
                }
            }
        }
        __syncthreads();
        if (J != I && tid < 128) {
            atomicAdd(&g_rowsum[J * 128 + tid],
                      csum2[0][tid] + csum2[1][tid] + csum2[2][tid] + csum2[3][tid]);
        }
        __syncthreads();   // csum read done + buffer slot free for reuse

        I = In; J = Jn; slot ^= 1;
    }
}

// ===================== K3: log + final reduction =====================

__global__ void __launch_bounds__(1024) k3_reduce(float* __restrict__ out) {
    const int t = threadIdx.x;
    float s = 0.0f;
    #pragma unroll
    for (int i = t; i < NTOT; i += 1024) s += logf(g_rowsum[i] - EXP_DIAG);
    #pragma unroll
    for (int r = t; r < BATCH; r += 1024) s -= 2.0f * g_pos[r];
    #pragma unroll
    for (int o = 16; o; o >>= 1) s += __shfl_xor_sync(0xffffffffu, s, o);
    __shared__ float red[32];
    if ((t & 31) == 0) red[t >> 5] = s;
    __syncthreads();
    if (t == 0) {
        float tot = 0.0f;
        #pragma unroll
        for (int w = 0; w < 32; w++) tot += red[w];
        out[0] = tot / (float)NTOT;
    }
}

// ===================== launch =====================

extern "C" void kernel_launch(void* const* d_in, const int* in_sizes, int n_in,
                              void* d_out, int out_size) {
    const float* zi = (const float*)d_in[0];
    const float* zj = (const float*)d_in[1];
    float* out = (float*)d_out;

    cudaFuncSetAttribute(k2_simsum, cudaFuncAttributeMaxDynamicSharedMemorySize, SMEM_BYTES);

    k1_normalize<<<BATCH / 8, 256>>>(zi, zj);
    k2_simsum<<<GRID_K2, 256, SMEM_BYTES>>>();
    k3_reduce<<<1, 1024>>>(out);
}